// round 16
// baseline (speedup 1.0000x reference)
#include <cuda_runtime.h>
#include <math.h>

#define NRES  2048
#define CDIM  256
#define HEADS 8
#define CH    32
#define PQ    8
#define PV    12
#define CZ    32
#define BQ    32
#define BK    128
#define NBLK  64
#define PADK  48
#define PROJW 1440
#define CATW  704
#define NPTS  224

// ---------------- scratch ----------------
__device__ float2 g_Wgb2[CDIM*512];     // pre-split (hi,lo) weights
__device__ float  g_bgb[512];
__device__ float2 g_Wcat2[CDIM*PROJW];
__device__ float2 g_Wout2[CATW*CDIM];
__device__ float  g_gb[NRES*512];
__device__ float  g_snew[NRES*CDIM];
__device__ float  g_proj[NRES*PROJW];
__device__ float  g_pts[NRES*NPTS*3];
__device__ float  g_bbias[NBLK*HEADS*BQ*BK];   // bias in, probs out (in-place)
__device__ float  g_pz[NBLK*BQ*BK*8];
__device__ float  g_cat[NRES*CATW];

// ---------------- tf32 split helpers ----------------
__device__ __forceinline__ void tf32_split(float x, unsigned& hi, unsigned& lo) {
    asm("cvt.rna.tf32.f32 %0, %1;" : "=r"(hi) : "f"(x));
    float rem = x - __uint_as_float(hi);
    asm("cvt.rna.tf32.f32 %0, %1;" : "=r"(lo) : "f"(rem));
}
__device__ __forceinline__ float2 tf32_split2(float x) {
    unsigned hi, lo;
    tf32_split(x, hi, lo);
    return make_float2(__uint_as_float(hi), __uint_as_float(lo));
}

// ---------------- weight concat + pre-split ----------------
__global__ void concat_wgb_kernel(const float* __restrict__ Wg, const float* __restrict__ bg,
                                  const float* __restrict__ Wbeta, const float* __restrict__ bbeta) {
    int idx = blockIdx.x*blockDim.x + threadIdx.x;
    if (idx < CDIM*512) {
        int r = idx / 512, c = idx % 512;
        float v = (c < 256) ? Wg[r*256 + c] : Wbeta[r*256 + (c-256)];
        g_Wgb2[idx] = tf32_split2(v);
    }
    if (idx < 512) g_bgb[idx] = (idx < 256) ? bg[idx] : bbeta[idx-256];
}

__global__ void concat_wcat_kernel(const float* __restrict__ Wq, const float* __restrict__ Wk,
                                   const float* __restrict__ Wv, const float* __restrict__ Wqp,
                                   const float* __restrict__ Wkvp) {
    int idx = blockIdx.x*blockDim.x + threadIdx.x;
    if (idx >= CDIM*PROJW) return;
    int r = idx / PROJW, c = idx % PROJW;
    float v;
    if      (c < 256) v = Wq[r*256 + c];
    else if (c < 512) v = Wk[r*256 + (c-256)];
    else if (c < 768) v = Wv[r*256 + (c-512)];
    else if (c < 960) v = Wqp[r*192 + (c-768)];
    else              v = Wkvp[r*480 + (c-960)];
    g_Wcat2[idx] = tf32_split2(v);
}

__global__ void split_wout_kernel(const float* __restrict__ Wout) {
    int idx = blockIdx.x*blockDim.x + threadIdx.x;
    if (idx < CATW*CDIM) g_Wout2[idx] = tf32_split2(Wout[idx]);
}

// ---------------- TF32 tensor-core GEMM, pre-split B, 32x64 tiles ----------------
// C = A(MxK) @ B2(KxN packed hi/lo) [+bias].  M%32==0, K%16==0, N%2==0.
// 128 threads = 4 warps (2 m-warps x 2 n-warps). BM=32, BN=64, BK=16.
#define MMA_TF32(d, a, b) \
    asm volatile("mma.sync.aligned.m16n8k8.row.col.f32.tf32.tf32.f32 " \
        "{%0,%1,%2,%3}, {%4,%5,%6,%7}, {%8,%9}, {%0,%1,%2,%3};" \
        : "+f"((d)[0]), "+f"((d)[1]), "+f"((d)[2]), "+f"((d)[3]) \
        : "r"((a)[0]), "r"((a)[1]), "r"((a)[2]), "r"((a)[3]), \
          "r"((b)[0]), "r"((b)[1]))

__global__ void gemm_tf32_kernel(const float* __restrict__ A, const float2* __restrict__ B2,
                                 const float* __restrict__ bias, float* __restrict__ C,
                                 int M, int N, int K) {
    __shared__ __align__(16) float  As[32][20];
    __shared__ __align__(16) float2 Bs2[16][66];
    const int bm   = blockIdx.y * 32;
    const int bn   = blockIdx.x * 64;
    const int tid  = threadIdx.x;     // 128
    const int lane = tid & 31;
    const int warp = tid >> 5;        // 0..3
    const int wm   = warp >> 1;       // 0..1
    const int wn   = warp & 1;        // 0..1
    const int gid  = lane >> 2;       // 0..7
    const int tig  = lane & 3;        // 0..3

    float d[4][4];
#pragma unroll
    for (int t = 0; t < 4; t++)
#pragma unroll
        for (int j = 0; j < 4; j++) d[t][j] = 0.f;

    const int arow = tid >> 2;        // 0..31
    const int ac4  = tid & 3;         // 0..3

    for (int k0 = 0; k0 < K; k0 += 16) {
        // A tile: 32 x 16 floats -> one float4 per thread
        {
            float4 a4 = *(const float4*)(A + (size_t)(bm + arow)*K + k0 + ac4*4);
            *(float4*)&As[arow][ac4*4] = a4;
        }
        // B tile: 16 x 64 float2 -> 512 float4 (= 2 float2 each) -> 4 per thread
#pragma unroll
        for (int t = 0; t < 4; t++) {
            int i    = tid + t*128;      // 0..511
            int kk   = i >> 5;           // 0..15
            int col4 = i & 31;           // 0..31 (pairs of float2)
            int gn   = bn + col4*2;
            float4 b4 = make_float4(0.f, 0.f, 0.f, 0.f);
            if (gn < N) b4 = *(const float4*)(B2 + (size_t)(k0 + kk)*N + gn);
            *(float4*)&Bs2[kk][col4*2] = b4;
        }
        __syncthreads();
#pragma unroll
        for (int kc = 0; kc < 16; kc += 8) {
            // A fragment (m16k8, row-major) + in-loop split
            unsigned ahi[4], alo[4];
#pragma unroll
            for (int r = 0; r < 4; r++) {
                int row = wm*16 + gid + (r & 1)*8;
                int col = kc + tig + (r >> 1)*4;
                tf32_split(As[row][col], ahi[r], alo[r]);
            }
#pragma unroll
            for (int nt = 0; nt < 4; nt++) {
                // B fragment: pre-split, one LDS.64 per element
                unsigned bhi[2], blo[2];
#pragma unroll
                for (int r = 0; r < 2; r++) {
                    float2 v = Bs2[kc + tig + r*4][wn*32 + nt*8 + gid];
                    bhi[r] = __float_as_uint(v.x);
                    blo[r] = __float_as_uint(v.y);
                }
                MMA_TF32(d[nt], ahi, bhi);
                MMA_TF32(d[nt], alo, bhi);
                MMA_TF32(d[nt], ahi, blo);
            }
        }
        __syncthreads();
    }
#pragma unroll
    for (int nt = 0; nt < 4; nt++) {
        int col = bn + wn*32 + nt*8 + tig*2;
        if (col < N) {
            int r0 = bm + wm*16 + gid;
            float b0 = bias ? bias[col]   : 0.f;
            float b1 = bias ? bias[col+1] : 0.f;
            *(float2*)(C + (size_t)r0*N + col)     = make_float2(d[nt][0] + b0, d[nt][1] + b1);
            *(float2*)(C + (size_t)(r0+8)*N + col) = make_float2(d[nt][2] + b0, d[nt][3] + b1);
        }
    }
}

// ---------------- s layernorm + modulate: warp per row ----------------
__global__ void ln_s_kernel(const float* __restrict__ s) {
    int row  = blockIdx.x*8 + (threadIdx.x >> 5);
    int lane = threadIdx.x & 31;
    const float4* sr = (const float4*)(s + (size_t)row*CDIM);
    float4 x0 = sr[lane];
    float4 x1 = sr[lane+32];
    float sum = x0.x+x0.y+x0.z+x0.w + x1.x+x1.y+x1.z+x1.w;
    float sq  = x0.x*x0.x+x0.y*x0.y+x0.z*x0.z+x0.w*x0.w
              + x1.x*x1.x+x1.y*x1.y+x1.z*x1.z+x1.w*x1.w;
#pragma unroll
    for (int o = 16; o > 0; o >>= 1) {
        sum += __shfl_xor_sync(0xffffffffu, sum, o);
        sq  += __shfl_xor_sync(0xffffffffu, sq,  o);
    }
    float mean = sum * (1.f/CDIM);
    float var  = sq  * (1.f/CDIM) - mean*mean;
    float rstd = rsqrtf(var + 1e-5f);
    const float4* gr = (const float4*)(g_gb + (size_t)row*512);
    float4 g0 = gr[lane],    g1 = gr[lane+32];
    float4 b0 = gr[lane+64], b1 = gr[lane+96];
    float4 o0, o1;
    o0.x = (x0.x-mean)*rstd*g0.x + b0.x;  o0.y = (x0.y-mean)*rstd*g0.y + b0.y;
    o0.z = (x0.z-mean)*rstd*g0.z + b0.z;  o0.w = (x0.w-mean)*rstd*g0.w + b0.w;
    o1.x = (x1.x-mean)*rstd*g1.x + b1.x;  o1.y = (x1.y-mean)*rstd*g1.y + b1.y;
    o1.z = (x1.z-mean)*rstd*g1.z + b1.z;  o1.w = (x1.w-mean)*rstd*g1.w + b1.w;
    float4* dst = (float4*)(g_snew + (size_t)row*CDIM);
    dst[lane]    = o0;
    dst[lane+32] = o1;
}

// ---------------- per-residue point frame transform ----------------
__global__ void pts_kernel(const float* __restrict__ trans, const float* __restrict__ rots) {
    int n = blockIdx.x;
    int p = threadIdx.x;     // 224
    __shared__ float R[9], t[3];
    if (threadIdx.x < 9) R[threadIdx.x] = rots[n*9 + threadIdx.x];
    if (threadIdx.x < 3) t[threadIdx.x] = trans[n*3 + threadIdx.x];
    __syncthreads();
    const float* src = g_proj + (size_t)n*PROJW + 768 + p*3;
    float x = src[0], y = src[1], z = src[2];
    float* dst = g_pts + ((size_t)n*NPTS + p)*3;
    dst[0] = R[0]*x + R[1]*y + R[2]*z + t[0];
    dst[1] = R[3]*x + R[4]*y + R[5]*z + t[1];
    dst[2] = R[6]*x + R[7]*y + R[8]*z + t[2];
}

// ---------------- z: layernorm*g+b, b-bias and pair_z ----------------
__global__ void zln_kernel(const float* __restrict__ z, const float* __restrict__ Wb,
                           const float* __restrict__ Wdz, const float* __restrict__ gz,
                           const float* __restrict__ bz) {
    __shared__ float sWb[CZ*8], sWdz[CZ*8], sgz[CZ], sbz[CZ];
    int tid = threadIdx.x;   // 256
    sWb[tid]  = Wb[tid];
    sWdz[tid] = Wdz[tid];
    if (tid < CZ) { sgz[tid] = gz[tid]; sbz[tid] = bz[tid]; }
    __syncthreads();

    int pair = blockIdx.x*256 + tid;
    const float4* zr = (const float4*)(z + (size_t)pair * CZ);
    float v[CZ];
    float sum = 0.f, sq = 0.f;
#pragma unroll
    for (int c4 = 0; c4 < 8; c4++) {
        float4 x4 = zr[c4];
        v[c4*4+0]=x4.x; v[c4*4+1]=x4.y; v[c4*4+2]=x4.z; v[c4*4+3]=x4.w;
        sum += x4.x+x4.y+x4.z+x4.w;
        sq  += x4.x*x4.x+x4.y*x4.y+x4.z*x4.z+x4.w*x4.w;
    }
    float mean = sum * (1.f/CZ);
    float var  = sq  * (1.f/CZ) - mean*mean;
    float rstd = rsqrtf(var + 1e-5f);
#pragma unroll
    for (int c = 0; c < CZ; c++) v[c] = (v[c]-mean)*rstd*sgz[c] + sbz[c];

    float ob[8], op[8];
#pragma unroll
    for (int h = 0; h < 8; h++) { ob[h] = 0.f; op[h] = 0.f; }
#pragma unroll
    for (int c = 0; c < CZ; c++) {
        float x = v[c];
#pragma unroll
        for (int h = 0; h < 8; h++) {
            ob[h] += x * sWb[c*8 + h];
            op[h] += x * sWdz[c*8 + h];
        }
    }
    int k  = pair & 127;
    int q  = (pair >> 7) & 31;
    int nb = pair >> 12;
#pragma unroll
    for (int h = 0; h < 8; h++)
        g_bbias[(((nb*HEADS + h)*BQ + q)*BK) + k] = ob[h] * 0.5773502691896258f;
    float* pzd = g_pz + (size_t)pair * 8;
#pragma unroll
    for (int c4 = 0; c4 < 2; c4++)
        *(float4*)(pzd + c4*4) = make_float4(op[c4*4], op[c4*4+1], op[c4*4+2], op[c4*4+3]);
}

// ---------------- attention phase 1: scores + softmax -> probs in g_bbias ----------------
#define SCORE_SMEM_FLOATS (32*33 + 128*33 + 32*25 + 128*25 + 32*129 + 128 + 32)

__global__ void attn_score_kernel(const float* __restrict__ smaskp, const float* __restrict__ headw) {
    extern __shared__ float sm[];
    float* qs  = sm;               // [32][33]
    float* ks  = qs  + 32*33;      // [128][33]
    float* qp  = ks  + 128*33;     // [32][25]
    float* kp  = qp  + 32*25;      // [128][25]
    float* am  = kp  + 128*25;     // [32][129]
    float* mk  = am  + 32*129;     // [128]
    float* smq = mk  + 128;        // [32]

    const int nb  = blockIdx.x;
    const int h   = blockIdx.y;
    const int tid = threadIdx.x;   // 128

    for (int i = tid; i < 32*32; i += 128) {
        int q = i >> 5, c = i & 31;
        qs[q*33 + c] = g_proj[(size_t)(nb*BQ + q)*PROJW + h*CH + c];
    }
    for (int i = tid; i < 128*32; i += 128) {
        int k = i >> 5, c = i & 31;
        int kidx = nb*BQ + k - PADK;
        bool valid = (kidx >= 0 && kidx < NRES);
        ks[k*33 + c] = valid ? g_proj[(size_t)kidx*PROJW + 256 + h*CH + c] : 0.f;
    }
    for (int i = tid; i < 32*24; i += 128) {
        int q = i / 24, j = i % 24;
        qp[q*25 + j] = g_pts[(((size_t)(nb*BQ + q))*NPTS + h*PQ + j/3)*3 + (j%3)];
    }
    for (int i = tid; i < 128*24; i += 128) {
        int k = i / 24, j = i % 24;
        int kidx = nb*BQ + k - PADK;
        bool valid = (kidx >= 0 && kidx < NRES);
        kp[k*25 + j] = valid ? g_pts[((size_t)kidx*NPTS + 64 + h*20 + j/3)*3 + (j%3)] : 0.f;
    }
    for (int i = tid; i < 32*128; i += 128) {
        int q = i >> 7, k = i & 127;
        am[q*129 + k] = g_bbias[(size_t)((nb*HEADS + h)*BQ + q)*BK + k];
    }
    {
        int kidx = nb*BQ + tid - PADK;
        mk[tid] = (kidx >= 0 && kidx < NRES) ? smaskp[kidx] : 0.f;
        if (tid < 32) smq[tid] = smaskp[nb*BQ + tid];
    }
    __syncthreads();

    float hww = headw[h];
    hww = ((hww > 20.f) ? hww : log1pf(expf(hww))) * 0.09622504486493763f; // softplus*sqrt(1/108)

    float kreg[32], kpr[24];
#pragma unroll
    for (int c = 0; c < 32; c++) kreg[c] = ks[tid*33 + c];
#pragma unroll
    for (int j = 0; j < 24; j++) kpr[j] = kp[tid*25 + j];
    const float maskk = mk[tid];

    for (int q = 0; q < 32; q++) {
        float dot = 0.f;
#pragma unroll
        for (int c = 0; c < 32; c++) dot += qs[q*33 + c] * kreg[c];
        float d2 = 0.f;
#pragma unroll
        for (int p = 0; p < 8; p++) {
            float dx = qp[q*25 + p*3 + 0] - kpr[p*3 + 0];
            float dy = qp[q*25 + p*3 + 1] - kpr[p*3 + 1];
            float dz = qp[q*25 + p*3 + 2] - kpr[p*3 + 2];
            d2 += dx*dx + dy*dy + dz*dz;
        }
        float sc = dot * 0.10206207261596577f
                 + am[q*129 + tid]
                 - 0.5f * hww * d2
                 + 1e8f * (smq[q]*maskk - 1.f);
        am[q*129 + tid] = sc;
    }
    __syncthreads();

    // softmax: 4 threads per row
    {
        int q = tid >> 2, sub = tid & 3;
        float mx = -1e30f;
#pragma unroll
        for (int j = 0; j < 32; j++) mx = fmaxf(mx, am[q*129 + sub + 4*j]);
        mx = fmaxf(mx, __shfl_xor_sync(0xffffffffu, mx, 1));
        mx = fmaxf(mx, __shfl_xor_sync(0xffffffffu, mx, 2));
        float ssum = 0.f;
#pragma unroll
        for (int j = 0; j < 32; j++) {
            float e = expf(am[q*129 + sub + 4*j] - mx);
            am[q*129 + sub + 4*j] = e;
            ssum += e;
        }
        ssum += __shfl_xor_sync(0xffffffffu, ssum, 1);
        ssum += __shfl_xor_sync(0xffffffffu, ssum, 2);
        float inv = 1.f / ssum;
#pragma unroll
        for (int j = 0; j < 32; j++) am[q*129 + sub + 4*j] *= inv;
    }
    __syncthreads();

    for (int i = tid; i < 32*128; i += 128) {
        int q = i >> 7, k = i & 127;
        g_bbias[(size_t)((nb*HEADS + h)*BQ + q)*BK + k] = am[q*129 + k];
    }
}

// ---------------- attention phase 2: outputs ----------------
#define OUT_SMEM_FLOATS (32*129 + 128*33 + 128*37 + 96 + 288)

__global__ void attn_out_kernel(const float* __restrict__ trans, const float* __restrict__ rots) {
    extern __shared__ float sm[];
    float* am = sm;               // [32][129] probs
    float* vs = am + 32*129;      // [128][33]
    float* vp = vs + 128*33;      // [128][37]
    float* qt = vp + 128*37;      // [32][3]
    float* qR = qt + 96;          // [32][9]

    const int nb  = blockIdx.x;
    const int h   = blockIdx.y;
    const int tid = threadIdx.x;  // 128

    for (int i = tid; i < 32*128; i += 128) {
        int q = i >> 7, k = i & 127;
        am[q*129 + k] = g_bbias[(size_t)((nb*HEADS + h)*BQ + q)*BK + k];
    }
    for (int i = tid; i < 128*32; i += 128) {
        int k = i >> 5, c = i & 31;
        int kidx = nb*BQ + k - PADK;
        bool valid = (kidx >= 0 && kidx < NRES);
        vs[k*33 + c] = valid ? g_proj[(size_t)kidx*PROJW + 512 + h*CH + c] : 0.f;
    }
    for (int i = tid; i < 128*36; i += 128) {
        int k = i / 36, j = i % 36;
        int kidx = nb*BQ + k - PADK;
        bool valid = (kidx >= 0 && kidx < NRES);
        vp[k*37 + j] = valid ? g_pts[((size_t)kidx*NPTS + 64 + h*20 + 8 + j/3)*3 + (j%3)] : 0.f;
    }
    for (int i = tid; i < 96;  i += 128) qt[i] = trans[(nb*BQ + i/3)*3 + (i%3)];
    for (int i = tid; i < 288; i += 128) qR[i] = rots[(nb*BQ + i/9)*9 + (i%9)];
    __syncthreads();

    // o = a @ v
    {
        int c = tid & 31, qg = tid >> 5;
        for (int qq = 0; qq < 8; qq++) {
            int q = qg + 4*qq;
            float acc = 0.f;
            for (int k = 0; k < 128; k++) acc += am[q*129 + k] * vs[k*33 + c];
            g_cat[(size_t)(nb*BQ + q)*CATW + h*CH + c] = acc;
        }
    }

    // o_pt with fused frame inversion + norms
    for (int i = tid; i < 32*12; i += 128) {
        int q = i / 12, v = i % 12;
        float ax = 0.f, ay = 0.f, az = 0.f;
        const float* vpr = vp + v*3;
        const float* amr = am + q*129;
        for (int k = 0; k < 128; k++) {
            float a = amr[k];
            ax += a * vpr[k*37 + 0];
            ay += a * vpr[k*37 + 1];
            az += a * vpr[k*37 + 2];
        }
        float gx = ax - qt[q*3 + 0];
        float gy = ay - qt[q*3 + 1];
        float gz = az - qt[q*3 + 2];
        const float* R = qR + q*9;
        float lx = R[0]*gx + R[3]*gy + R[6]*gz;
        float ly = R[1]*gx + R[4]*gy + R[7]*gz;
        float lz = R[2]*gx + R[5]*gy + R[8]*gz;
        int n = nb*BQ + q;
        g_cat[(size_t)n*CATW + 256 + h*36 + v*3 + 0] = lx;
        g_cat[(size_t)n*CATW + 256 + h*36 + v*3 + 1] = ly;
        g_cat[(size_t)n*CATW + 256 + h*36 + v*3 + 2] = lz;
        g_cat[(size_t)n*CATW + 544 + h*12 + v] = sqrtf(lx*lx + ly*ly + lz*lz + 1e-8f);
    }

    // o_pair = a @ pair_z
    for (int i = tid; i < 32*8; i += 128) {
        int q = i >> 3, c8 = i & 7;
        const float* pzr = g_pz + ((size_t)(nb*BQ + q)*BK)*8 + c8;
        float acc = 0.f;
        for (int k = 0; k < 128; k++) acc += am[q*129 + k] * pzr[k*8];
        g_cat[(size_t)(nb*BQ + q)*CATW + 640 + h*8 + c8] = acc;
    }
}

// ---------------- launch ----------------
static float* symaddr(const void* sym) {
    void* p = nullptr;
    cudaGetSymbolAddress(&p, sym);
    return (float*)p;
}

extern "C" void kernel_launch(void* const* d_in, const int* in_sizes, int n_in,
                              void* d_out, int out_size) {
    const float* s      = (const float*)d_in[0];
    const float* cond   = (const float*)d_in[1];
    const float* z      = (const float*)d_in[2];
    const float* trans  = (const float*)d_in[3];
    const float* rots   = (const float*)d_in[4];
    const float* smask  = (const float*)d_in[5];
    const float* Wq     = (const float*)d_in[6];
    const float* Wk     = (const float*)d_in[7];
    const float* Wv     = (const float*)d_in[8];
    const float* Wqp    = (const float*)d_in[9];
    const float* Wkvp   = (const float*)d_in[10];
    const float* Wb     = (const float*)d_in[11];
    const float* Wdz    = (const float*)d_in[12];
    const float* headw  = (const float*)d_in[13];
    const float* Wout   = (const float*)d_in[14];
    const float* Wg     = (const float*)d_in[15];
    const float* bg     = (const float*)d_in[16];
    const float* Wbeta  = (const float*)d_in[17];
    const float* bbeta  = (const float*)d_in[18];
    const float* gz     = (const float*)d_in[19];
    const float* bz     = (const float*)d_in[20];
    float* out = (float*)d_out;

    float*  p_bgb   = symaddr(g_bgb);
    float*  p_gb    = symaddr(g_gb);
    float*  p_snew  = symaddr(g_snew);
    float*  p_proj  = symaddr(g_proj);
    float*  p_cat   = symaddr(g_cat);
    float2* p_Wgb2  = (float2*)symaddr(g_Wgb2);
    float2* p_Wcat2 = (float2*)symaddr(g_Wcat2);
    float2* p_Wout2 = (float2*)symaddr(g_Wout2);

    const size_t score_smem = SCORE_SMEM_FLOATS * sizeof(float);
    const size_t out_smem   = OUT_SMEM_FLOATS   * sizeof(float);
    cudaFuncSetAttribute(attn_score_kernel, cudaFuncAttributeMaxDynamicSharedMemorySize, (int)score_smem);
    cudaFuncSetAttribute(attn_out_kernel,   cudaFuncAttributeMaxDynamicSharedMemorySize, (int)out_smem);

    // zln first (independent)
    zln_kernel<<<(NBLK*BQ*BK)/256, 256>>>(z, Wb, Wdz, gz, bz);

    // weight concats + pre-split
    concat_wgb_kernel<<<(CDIM*512 + 255)/256, 256>>>(Wg, bg, Wbeta, bbeta);
    concat_wcat_kernel<<<(CDIM*PROJW + 255)/256, 256>>>(Wq, Wk, Wv, Wqp, Wkvp);
    split_wout_kernel<<<(CATW*CDIM + 255)/256, 256>>>(Wout);

    // gb = cond @ [Wg|Wbeta] + bias   (M=2048, N=512, K=256) -> 8x64 = 512 blocks
    gemm_tf32_kernel<<<dim3(512/64, NRES/32), 128>>>(cond, p_Wgb2, p_bgb, p_gb, NRES, 512, CDIM);

    // s_new = ln(s)*gamma + beta
    ln_s_kernel<<<NRES/8, 256>>>(s);

    // proj = s_new @ Wcat   (M=2048, N=1440, K=256) -> 23x64 = 1472 blocks
    gemm_tf32_kernel<<<dim3((PROJW + 63)/64, NRES/32), 128>>>(p_snew, p_Wcat2, nullptr, p_proj, NRES, PROJW, CDIM);

    // frame-transform points
    pts_kernel<<<NRES, NPTS>>>(trans, rots);

    // attention (split)
    attn_score_kernel<<<dim3(NBLK, HEADS), 128, score_smem>>>(smask, headw);
    attn_out_kernel<<<dim3(NBLK, HEADS), 128, out_smem>>>(trans, rots);

    // out = cat @ Wout   (M=2048, N=256, K=704) -> 4x64 = 256 blocks
    gemm_tf32_kernel<<<dim3(CDIM/64, NRES/32), 128>>>(p_cat, p_Wout2, nullptr, out, NRES, CDIM, CATW);
}

// round 17
// speedup vs baseline: 1.0440x; 1.0440x over previous
#include <cuda_runtime.h>
#include <math.h>

#define NRES  2048
#define CDIM  256
#define HEADS 8
#define CH    32
#define PQ    8
#define PV    12
#define CZ    32
#define BQ    32
#define BK    128
#define NBLK  64
#define PADK  48
#define PROJW 1440
#define CATW  704
#define NPTS  224

// ---------------- scratch ----------------
__device__ float2 g_Wgb2[CDIM*512];     // pre-split (hi,lo) weights
__device__ float  g_bgb[512];
__device__ float2 g_Wcat2[CDIM*PROJW];
__device__ float2 g_Wout2[CATW*CDIM];
__device__ float  g_gb[NRES*512];
__device__ float  g_snew[NRES*CDIM];
__device__ float  g_proj[NRES*PROJW];
__device__ float  g_pts[NRES*NPTS*3];
__device__ float  g_bbias[NBLK*HEADS*BQ*BK];   // bias in, probs out (in-place)
__device__ float  g_pz[NBLK*BQ*BK*8];
__device__ float  g_cat[NRES*CATW];

// ---------------- tf32 split helpers ----------------
__device__ __forceinline__ void tf32_split(float x, unsigned& hi, unsigned& lo) {
    asm("cvt.rna.tf32.f32 %0, %1;" : "=r"(hi) : "f"(x));
    float rem = x - __uint_as_float(hi);
    asm("cvt.rna.tf32.f32 %0, %1;" : "=r"(lo) : "f"(rem));
}
__device__ __forceinline__ float2 tf32_split2(float x) {
    unsigned hi, lo;
    tf32_split(x, hi, lo);
    return make_float2(__uint_as_float(hi), __uint_as_float(lo));
}

// ---------------- weight concat + pre-split ----------------
__global__ void concat_wgb_kernel(const float* __restrict__ Wg, const float* __restrict__ bg,
                                  const float* __restrict__ Wbeta, const float* __restrict__ bbeta) {
    int idx = blockIdx.x*blockDim.x + threadIdx.x;
    if (idx < CDIM*512) {
        int r = idx / 512, c = idx % 512;
        float v = (c < 256) ? Wg[r*256 + c] : Wbeta[r*256 + (c-256)];
        g_Wgb2[idx] = tf32_split2(v);
    }
    if (idx < 512) g_bgb[idx] = (idx < 256) ? bg[idx] : bbeta[idx-256];
}

__global__ void concat_wcat_kernel(const float* __restrict__ Wq, const float* __restrict__ Wk,
                                   const float* __restrict__ Wv, const float* __restrict__ Wqp,
                                   const float* __restrict__ Wkvp) {
    int idx = blockIdx.x*blockDim.x + threadIdx.x;
    if (idx >= CDIM*PROJW) return;
    int r = idx / PROJW, c = idx % PROJW;
    float v;
    if      (c < 256) v = Wq[r*256 + c];
    else if (c < 512) v = Wk[r*256 + (c-256)];
    else if (c < 768) v = Wv[r*256 + (c-512)];
    else if (c < 960) v = Wqp[r*192 + (c-768)];
    else              v = Wkvp[r*480 + (c-960)];
    g_Wcat2[idx] = tf32_split2(v);
}

__global__ void split_wout_kernel(const float* __restrict__ Wout) {
    int idx = blockIdx.x*blockDim.x + threadIdx.x;   // 2 elems per thread
    int base = idx * 2;
    if (base < CATW*CDIM) {
        float2 v = *(const float2*)(Wout + base);
        g_Wout2[base]   = tf32_split2(v.x);
        g_Wout2[base+1] = tf32_split2(v.y);
    }
}

// ---------------- TF32 tensor-core GEMM, pre-split B, R14 geometry ----------------
// C = A(MxK) @ B2(KxN packed hi/lo) [+bias].  M%64==0, K%16==0, N%2==0.
// 256 threads = 8 warps (4 m-warps x 2 n-warps). BM=BN=64, BK=16.
#define MMA_TF32(d, a, b) \
    asm volatile("mma.sync.aligned.m16n8k8.row.col.f32.tf32.tf32.f32 " \
        "{%0,%1,%2,%3}, {%4,%5,%6,%7}, {%8,%9}, {%0,%1,%2,%3};" \
        : "+f"((d)[0]), "+f"((d)[1]), "+f"((d)[2]), "+f"((d)[3]) \
        : "r"((a)[0]), "r"((a)[1]), "r"((a)[2]), "r"((a)[3]), \
          "r"((b)[0]), "r"((b)[1]))

__global__ void gemm_tf32_kernel(const float* __restrict__ A, const float2* __restrict__ B2,
                                 const float* __restrict__ bias, float* __restrict__ C,
                                 int M, int N, int K) {
    __shared__ __align__(16) float  As[64][20];
    __shared__ __align__(16) float2 Bs2[16][66];
    const int bm   = blockIdx.y * 64;
    const int bn   = blockIdx.x * 64;
    const int tid  = threadIdx.x;     // 256
    const int lane = tid & 31;
    const int warp = tid >> 5;        // 0..7
    const int wm   = warp >> 1;       // 0..3
    const int wn   = warp & 1;        // 0..1
    const int gid  = lane >> 2;       // 0..7
    const int tig  = lane & 3;        // 0..3

    float d[4][4];
#pragma unroll
    for (int t = 0; t < 4; t++)
#pragma unroll
        for (int j = 0; j < 4; j++) d[t][j] = 0.f;

    const int arow = tid >> 2;        // 0..63
    const int ac4  = tid & 3;         // 0..3

    for (int k0 = 0; k0 < K; k0 += 16) {
        // A tile: 64 x 16 floats -> one float4 per thread
        {
            float4 a4 = *(const float4*)(A + (size_t)(bm + arow)*K + k0 + ac4*4);
            *(float4*)&As[arow][ac4*4] = a4;
        }
        // B tile: 16 x 64 float2 = 512 float4 -> 2 per thread
#pragma unroll
        for (int t = 0; t < 2; t++) {
            int i    = tid + t*256;      // 0..511
            int kk   = i >> 5;           // 0..15
            int col4 = i & 31;           // pair-of-float2 index 0..31
            int gn   = bn + col4*2;
            float4 b4 = make_float4(0.f, 0.f, 0.f, 0.f);
            if (gn < N) b4 = *(const float4*)(B2 + (size_t)(k0 + kk)*N + gn);
            *(float4*)&Bs2[kk][col4*2] = b4;
        }
        __syncthreads();
#pragma unroll
        for (int kc = 0; kc < 16; kc += 8) {
            // A fragment (m16k8, row-major) + in-loop split
            unsigned ahi[4], alo[4];
#pragma unroll
            for (int r = 0; r < 4; r++) {
                int row = wm*16 + gid + (r & 1)*8;
                int col = kc + tig + (r >> 1)*4;
                tf32_split(As[row][col], ahi[r], alo[r]);
            }
#pragma unroll
            for (int nt = 0; nt < 4; nt++) {
                // B fragment: pre-split, one LDS.64 per element
                unsigned bhi[2], blo[2];
#pragma unroll
                for (int r = 0; r < 2; r++) {
                    float2 v = Bs2[kc + tig + r*4][wn*32 + nt*8 + gid];
                    bhi[r] = __float_as_uint(v.x);
                    blo[r] = __float_as_uint(v.y);
                }
                MMA_TF32(d[nt], ahi, bhi);
                MMA_TF32(d[nt], alo, bhi);
                MMA_TF32(d[nt], ahi, blo);
            }
        }
        __syncthreads();
    }
#pragma unroll
    for (int nt = 0; nt < 4; nt++) {
        int col = bn + wn*32 + nt*8 + tig*2;
        if (col < N) {
            int r0 = bm + wm*16 + gid;
            float b0 = bias ? bias[col]   : 0.f;
            float b1 = bias ? bias[col+1] : 0.f;
            *(float2*)(C + (size_t)r0*N + col)     = make_float2(d[nt][0] + b0, d[nt][1] + b1);
            *(float2*)(C + (size_t)(r0+8)*N + col) = make_float2(d[nt][2] + b0, d[nt][3] + b1);
        }
    }
}

// ---------------- s layernorm + modulate: warp per row ----------------
__global__ void ln_s_kernel(const float* __restrict__ s) {
    int row  = blockIdx.x*8 + (threadIdx.x >> 5);
    int lane = threadIdx.x & 31;
    const float4* sr = (const float4*)(s + (size_t)row*CDIM);
    float4 x0 = sr[lane];
    float4 x1 = sr[lane+32];
    float sum = x0.x+x0.y+x0.z+x0.w + x1.x+x1.y+x1.z+x1.w;
    float sq  = x0.x*x0.x+x0.y*x0.y+x0.z*x0.z+x0.w*x0.w
              + x1.x*x1.x+x1.y*x1.y+x1.z*x1.z+x1.w*x1.w;
#pragma unroll
    for (int o = 16; o > 0; o >>= 1) {
        sum += __shfl_xor_sync(0xffffffffu, sum, o);
        sq  += __shfl_xor_sync(0xffffffffu, sq,  o);
    }
    float mean = sum * (1.f/CDIM);
    float var  = sq  * (1.f/CDIM) - mean*mean;
    float rstd = rsqrtf(var + 1e-5f);
    const float4* gr = (const float4*)(g_gb + (size_t)row*512);
    float4 g0 = gr[lane],    g1 = gr[lane+32];
    float4 b0 = gr[lane+64], b1 = gr[lane+96];
    float4 o0, o1;
    o0.x = (x0.x-mean)*rstd*g0.x + b0.x;  o0.y = (x0.y-mean)*rstd*g0.y + b0.y;
    o0.z = (x0.z-mean)*rstd*g0.z + b0.z;  o0.w = (x0.w-mean)*rstd*g0.w + b0.w;
    o1.x = (x1.x-mean)*rstd*g1.x + b1.x;  o1.y = (x1.y-mean)*rstd*g1.y + b1.y;
    o1.z = (x1.z-mean)*rstd*g1.z + b1.z;  o1.w = (x1.w-mean)*rstd*g1.w + b1.w;
    float4* dst = (float4*)(g_snew + (size_t)row*CDIM);
    dst[lane]    = o0;
    dst[lane+32] = o1;
}

// ---------------- per-residue point frame transform ----------------
__global__ void pts_kernel(const float* __restrict__ trans, const float* __restrict__ rots) {
    int n = blockIdx.x;
    int p = threadIdx.x;     // 224
    __shared__ float R[9], t[3];
    if (threadIdx.x < 9) R[threadIdx.x] = rots[n*9 + threadIdx.x];
    if (threadIdx.x < 3) t[threadIdx.x] = trans[n*3 + threadIdx.x];
    __syncthreads();
    const float* src = g_proj + (size_t)n*PROJW + 768 + p*3;
    float x = src[0], y = src[1], z = src[2];
    float* dst = g_pts + ((size_t)n*NPTS + p)*3;
    dst[0] = R[0]*x + R[1]*y + R[2]*z + t[0];
    dst[1] = R[3]*x + R[4]*y + R[5]*z + t[1];
    dst[2] = R[6]*x + R[7]*y + R[8]*z + t[2];
}

// ---------------- z: layernorm*g+b, b-bias and pair_z ----------------
__global__ void zln_kernel(const float* __restrict__ z, const float* __restrict__ Wb,
                           const float* __restrict__ Wdz, const float* __restrict__ gz,
                           const float* __restrict__ bz) {
    __shared__ float sWb[CZ*8], sWdz[CZ*8], sgz[CZ], sbz[CZ];
    int tid = threadIdx.x;   // 256
    sWb[tid]  = Wb[tid];
    sWdz[tid] = Wdz[tid];
    if (tid < CZ) { sgz[tid] = gz[tid]; sbz[tid] = bz[tid]; }
    __syncthreads();

    int pair = blockIdx.x*256 + tid;
    const float4* zr = (const float4*)(z + (size_t)pair * CZ);
    float v[CZ];
    float sum = 0.f, sq = 0.f;
#pragma unroll
    for (int c4 = 0; c4 < 8; c4++) {
        float4 x4 = zr[c4];
        v[c4*4+0]=x4.x; v[c4*4+1]=x4.y; v[c4*4+2]=x4.z; v[c4*4+3]=x4.w;
        sum += x4.x+x4.y+x4.z+x4.w;
        sq  += x4.x*x4.x+x4.y*x4.y+x4.z*x4.z+x4.w*x4.w;
    }
    float mean = sum * (1.f/CZ);
    float var  = sq  * (1.f/CZ) - mean*mean;
    float rstd = rsqrtf(var + 1e-5f);
#pragma unroll
    for (int c = 0; c < CZ; c++) v[c] = (v[c]-mean)*rstd*sgz[c] + sbz[c];

    float ob[8], op[8];
#pragma unroll
    for (int h = 0; h < 8; h++) { ob[h] = 0.f; op[h] = 0.f; }
#pragma unroll
    for (int c = 0; c < CZ; c++) {
        float x = v[c];
#pragma unroll
        for (int h = 0; h < 8; h++) {
            ob[h] += x * sWb[c*8 + h];
            op[h] += x * sWdz[c*8 + h];
        }
    }
    int k  = pair & 127;
    int q  = (pair >> 7) & 31;
    int nb = pair >> 12;
#pragma unroll
    for (int h = 0; h < 8; h++)
        g_bbias[(((nb*HEADS + h)*BQ + q)*BK) + k] = ob[h] * 0.5773502691896258f;
    float* pzd = g_pz + (size_t)pair * 8;
#pragma unroll
    for (int c4 = 0; c4 < 2; c4++)
        *(float4*)(pzd + c4*4) = make_float4(op[c4*4], op[c4*4+1], op[c4*4+2], op[c4*4+3]);
}

// ---------------- attention phase 1: scores + softmax -> probs in g_bbias ----------------
#define SCORE_SMEM_FLOATS (32*33 + 128*33 + 32*25 + 128*25 + 32*129 + 128 + 32)

__global__ void attn_score_kernel(const float* __restrict__ smaskp, const float* __restrict__ headw) {
    extern __shared__ float sm[];
    float* qs  = sm;               // [32][33]
    float* ks  = qs  + 32*33;      // [128][33]
    float* qp  = ks  + 128*33;     // [32][25]
    float* kp  = qp  + 32*25;      // [128][25]
    float* am  = kp  + 128*25;     // [32][129]
    float* mk  = am  + 32*129;     // [128]
    float* smq = mk  + 128;        // [32]

    const int nb  = blockIdx.x;
    const int h   = blockIdx.y;
    const int tid = threadIdx.x;   // 128

    for (int i = tid; i < 32*32; i += 128) {
        int q = i >> 5, c = i & 31;
        qs[q*33 + c] = g_proj[(size_t)(nb*BQ + q)*PROJW + h*CH + c];
    }
    for (int i = tid; i < 128*32; i += 128) {
        int k = i >> 5, c = i & 31;
        int kidx = nb*BQ + k - PADK;
        bool valid = (kidx >= 0 && kidx < NRES);
        ks[k*33 + c] = valid ? g_proj[(size_t)kidx*PROJW + 256 + h*CH + c] : 0.f;
    }
    for (int i = tid; i < 32*24; i += 128) {
        int q = i / 24, j = i % 24;
        qp[q*25 + j] = g_pts[(((size_t)(nb*BQ + q))*NPTS + h*PQ + j/3)*3 + (j%3)];
    }
    for (int i = tid; i < 128*24; i += 128) {
        int k = i / 24, j = i % 24;
        int kidx = nb*BQ + k - PADK;
        bool valid = (kidx >= 0 && kidx < NRES);
        kp[k*25 + j] = valid ? g_pts[((size_t)kidx*NPTS + 64 + h*20 + j/3)*3 + (j%3)] : 0.f;
    }
    for (int i = tid; i < 32*128; i += 128) {
        int q = i >> 7, k = i & 127;
        am[q*129 + k] = g_bbias[(size_t)((nb*HEADS + h)*BQ + q)*BK + k];
    }
    {
        int kidx = nb*BQ + tid - PADK;
        mk[tid] = (kidx >= 0 && kidx < NRES) ? smaskp[kidx] : 0.f;
        if (tid < 32) smq[tid] = smaskp[nb*BQ + tid];
    }
    __syncthreads();

    float hww = headw[h];
    hww = ((hww > 20.f) ? hww : log1pf(expf(hww))) * 0.09622504486493763f; // softplus*sqrt(1/108)

    float kreg[32], kpr[24];
#pragma unroll
    for (int c = 0; c < 32; c++) kreg[c] = ks[tid*33 + c];
#pragma unroll
    for (int j = 0; j < 24; j++) kpr[j] = kp[tid*25 + j];
    const float maskk = mk[tid];

    for (int q = 0; q < 32; q++) {
        float dot = 0.f;
#pragma unroll
        for (int c = 0; c < 32; c++) dot += qs[q*33 + c] * kreg[c];
        float d2 = 0.f;
#pragma unroll
        for (int p = 0; p < 8; p++) {
            float dx = qp[q*25 + p*3 + 0] - kpr[p*3 + 0];
            float dy = qp[q*25 + p*3 + 1] - kpr[p*3 + 1];
            float dz = qp[q*25 + p*3 + 2] - kpr[p*3 + 2];
            d2 += dx*dx + dy*dy + dz*dz;
        }
        float sc = dot * 0.10206207261596577f
                 + am[q*129 + tid]
                 - 0.5f * hww * d2
                 + 1e8f * (smq[q]*maskk - 1.f);
        am[q*129 + tid] = sc;
    }
    __syncthreads();

    // softmax: 4 threads per row
    {
        int q = tid >> 2, sub = tid & 3;
        float mx = -1e30f;
#pragma unroll
        for (int j = 0; j < 32; j++) mx = fmaxf(mx, am[q*129 + sub + 4*j]);
        mx = fmaxf(mx, __shfl_xor_sync(0xffffffffu, mx, 1));
        mx = fmaxf(mx, __shfl_xor_sync(0xffffffffu, mx, 2));
        float ssum = 0.f;
#pragma unroll
        for (int j = 0; j < 32; j++) {
            float e = expf(am[q*129 + sub + 4*j] - mx);
            am[q*129 + sub + 4*j] = e;
            ssum += e;
        }
        ssum += __shfl_xor_sync(0xffffffffu, ssum, 1);
        ssum += __shfl_xor_sync(0xffffffffu, ssum, 2);
        float inv = 1.f / ssum;
#pragma unroll
        for (int j = 0; j < 32; j++) am[q*129 + sub + 4*j] *= inv;
    }
    __syncthreads();

    for (int i = tid; i < 32*128; i += 128) {
        int q = i >> 7, k = i & 127;
        g_bbias[(size_t)((nb*HEADS + h)*BQ + q)*BK + k] = am[q*129 + k];
    }
}

// ---------------- attention phase 2: outputs ----------------
#define OUT_SMEM_FLOATS (32*129 + 128*33 + 128*37 + 96 + 288)

__global__ void attn_out_kernel(const float* __restrict__ trans, const float* __restrict__ rots) {
    extern __shared__ float sm[];
    float* am = sm;               // [32][129] probs
    float* vs = am + 32*129;      // [128][33]
    float* vp = vs + 128*33;      // [128][37]
    float* qt = vp + 128*37;      // [32][3]
    float* qR = qt + 96;          // [32][9]

    const int nb  = blockIdx.x;
    const int h   = blockIdx.y;
    const int tid = threadIdx.x;  // 128

    for (int i = tid; i < 32*128; i += 128) {
        int q = i >> 7, k = i & 127;
        am[q*129 + k] = g_bbias[(size_t)((nb*HEADS + h)*BQ + q)*BK + k];
    }
    for (int i = tid; i < 128*32; i += 128) {
        int k = i >> 5, c = i & 31;
        int kidx = nb*BQ + k - PADK;
        bool valid = (kidx >= 0 && kidx < NRES);
        vs[k*33 + c] = valid ? g_proj[(size_t)kidx*PROJW + 512 + h*CH + c] : 0.f;
    }
    for (int i = tid; i < 128*36; i += 128) {
        int k = i / 36, j = i % 36;
        int kidx = nb*BQ + k - PADK;
        bool valid = (kidx >= 0 && kidx < NRES);
        vp[k*37 + j] = valid ? g_pts[((size_t)kidx*NPTS + 64 + h*20 + 8 + j/3)*3 + (j%3)] : 0.f;
    }
    for (int i = tid; i < 96;  i += 128) qt[i] = trans[(nb*BQ + i/3)*3 + (i%3)];
    for (int i = tid; i < 288; i += 128) qR[i] = rots[(nb*BQ + i/9)*9 + (i%9)];
    __syncthreads();

    // o = a @ v
    {
        int c = tid & 31, qg = tid >> 5;
        for (int qq = 0; qq < 8; qq++) {
            int q = qg + 4*qq;
            float acc = 0.f;
            for (int k = 0; k < 128; k++) acc += am[q*129 + k] * vs[k*33 + c];
            g_cat[(size_t)(nb*BQ + q)*CATW + h*CH + c] = acc;
        }
    }

    // o_pt with fused frame inversion + norms
    for (int i = tid; i < 32*12; i += 128) {
        int q = i / 12, v = i % 12;
        float ax = 0.f, ay = 0.f, az = 0.f;
        const float* vpr = vp + v*3;
        const float* amr = am + q*129;
        for (int k = 0; k < 128; k++) {
            float a = amr[k];
            ax += a * vpr[k*37 + 0];
            ay += a * vpr[k*37 + 1];
            az += a * vpr[k*37 + 2];
        }
        float gx = ax - qt[q*3 + 0];
        float gy = ay - qt[q*3 + 1];
        float gz = az - qt[q*3 + 2];
        const float* R = qR + q*9;
        float lx = R[0]*gx + R[3]*gy + R[6]*gz;
        float ly = R[1]*gx + R[4]*gy + R[7]*gz;
        float lz = R[2]*gx + R[5]*gy + R[8]*gz;
        int n = nb*BQ + q;
        g_cat[(size_t)n*CATW + 256 + h*36 + v*3 + 0] = lx;
        g_cat[(size_t)n*CATW + 256 + h*36 + v*3 + 1] = ly;
        g_cat[(size_t)n*CATW + 256 + h*36 + v*3 + 2] = lz;
        g_cat[(size_t)n*CATW + 544 + h*12 + v] = sqrtf(lx*lx + ly*ly + lz*lz + 1e-8f);
    }

    // o_pair = a @ pair_z
    for (int i = tid; i < 32*8; i += 128) {
        int q = i >> 3, c8 = i & 7;
        const float* pzr = g_pz + ((size_t)(nb*BQ + q)*BK)*8 + c8;
        float acc = 0.f;
        for (int k = 0; k < 128; k++) acc += am[q*129 + k] * pzr[k*8];
        g_cat[(size_t)(nb*BQ + q)*CATW + 640 + h*8 + c8] = acc;
    }
}

// ---------------- launch ----------------
static float* symaddr(const void* sym) {
    void* p = nullptr;
    cudaGetSymbolAddress(&p, sym);
    return (float*)p;
}

extern "C" void kernel_launch(void* const* d_in, const int* in_sizes, int n_in,
                              void* d_out, int out_size) {
    const float* s      = (const float*)d_in[0];
    const float* cond   = (const float*)d_in[1];
    const float* z      = (const float*)d_in[2];
    const float* trans  = (const float*)d_in[3];
    const float* rots   = (const float*)d_in[4];
    const float* smask  = (const float*)d_in[5];
    const float* Wq     = (const float*)d_in[6];
    const float* Wk     = (const float*)d_in[7];
    const float* Wv     = (const float*)d_in[8];
    const float* Wqp    = (const float*)d_in[9];
    const float* Wkvp   = (const float*)d_in[10];
    const float* Wb     = (const float*)d_in[11];
    const float* Wdz    = (const float*)d_in[12];
    const float* headw  = (const float*)d_in[13];
    const float* Wout   = (const float*)d_in[14];
    const float* Wg     = (const float*)d_in[15];
    const float* bg     = (const float*)d_in[16];
    const float* Wbeta  = (const float*)d_in[17];
    const float* bbeta  = (const float*)d_in[18];
    const float* gz     = (const float*)d_in[19];
    const float* bz     = (const float*)d_in[20];
    float* out = (float*)d_out;

    float*  p_bgb   = symaddr(g_bgb);
    float*  p_gb    = symaddr(g_gb);
    float*  p_snew  = symaddr(g_snew);
    float*  p_proj  = symaddr(g_proj);
    float*  p_cat   = symaddr(g_cat);
    float2* p_Wgb2  = (float2*)symaddr(g_Wgb2);
    float2* p_Wcat2 = (float2*)symaddr(g_Wcat2);
    float2* p_Wout2 = (float2*)symaddr(g_Wout2);

    const size_t score_smem = SCORE_SMEM_FLOATS * sizeof(float);
    const size_t out_smem   = OUT_SMEM_FLOATS   * sizeof(float);
    cudaFuncSetAttribute(attn_score_kernel, cudaFuncAttributeMaxDynamicSharedMemorySize, (int)score_smem);
    cudaFuncSetAttribute(attn_out_kernel,   cudaFuncAttributeMaxDynamicSharedMemorySize, (int)out_smem);

    // zln first (independent)
    zln_kernel<<<(NBLK*BQ*BK)/256, 256>>>(z, Wb, Wdz, gz, bz);

    // weight concats + pre-split
    concat_wgb_kernel<<<(CDIM*512 + 255)/256, 256>>>(Wg, bg, Wbeta, bbeta);
    concat_wcat_kernel<<<(CDIM*PROJW + 255)/256, 256>>>(Wq, Wk, Wv, Wqp, Wkvp);
    split_wout_kernel<<<(CATW*CDIM/2 + 255)/256, 256>>>(Wout);

    // gb = cond @ [Wg|Wbeta] + bias   (M=2048, N=512, K=256) -> 8x32 = 256 blocks
    gemm_tf32_kernel<<<dim3(512/64, NRES/64), 256>>>(cond, p_Wgb2, p_bgb, p_gb, NRES, 512, CDIM);

    // s_new = ln(s)*gamma + beta
    ln_s_kernel<<<NRES/8, 256>>>(s);

    // proj = s_new @ Wcat   (M=2048, N=1440, K=256) -> 23x32 = 736 blocks
    gemm_tf32_kernel<<<dim3((PROJW + 63)/64, NRES/64), 256>>>(p_snew, p_Wcat2, nullptr, p_proj, NRES, PROJW, CDIM);

    // frame-transform points
    pts_kernel<<<NRES, NPTS>>>(trans, rots);

    // attention (split)
    attn_score_kernel<<<dim3(NBLK, HEADS), 128, score_smem>>>(smask, headw);
    attn_out_kernel<<<dim3(NBLK, HEADS), 128, out_smem>>>(trans, rots);

    // out = cat @ Wout   (M=2048, N=256, K=704) -> 4x32 = 128 blocks
    gemm_tf32_kernel<<<dim3(CDIM/64, NRES/64), 256>>>(p_cat, p_Wout2, nullptr, out, NRES, CDIM, CATW);
}